// round 16
// baseline (speedup 1.0000x reference)
#include <cuda_runtime.h>
#include <cuda_fp16.h>
#include <mma.h>
#include <math.h>

using namespace nvcuda;

#define N_NODES 100000
#define IN_C    128
#define HEADS   4
#define OUT_C   64
#define HC      256           // HEADS*OUT_C
#define NE      1600000
#define ET      (NE + N_NODES)   // edges + self loops = 1,700,000
#define NEG_SLOPE 0.2f
#define BN_EPS  1e-5f

#define LDA 136               // sA row pitch (halves)
#define LDB 264               // sB row pitch (halves): 528B -> conflict-free LDSM

#define GEMM_BLOCKS ((N_NODES + 63) / 64)          // 1563
#define HIST_BLOCKS ((NE / 4 + 255) / 256)         // 1563
#define DOTS_BLOCKS ((N_NODES + 7) / 8)            // 12500
#define FUSED_BLOCKS (GEMM_BLOCKS + HIST_BLOCKS + DOTS_BLOCKS)

// ---------------- scratch (device globals; no allocations allowed) ----------
__device__ __align__(16) __half g_hh[(size_t)(N_NODES + 64) * HC]; // fp16 h (+pad tile)
__device__ __align__(16) __half g_Wh[IN_C * HC];   // W in fp16
__device__ float  g_u[2 * 4 * IN_C];               // u[sd][h][k] = (W @ att^T)
__device__ float4 g_asrc[N_NODES];
__device__ float4 g_adst[N_NODES];
__device__ int    g_deg[N_NODES];
__device__ int    g_off[N_NODES + 1];
__device__ unsigned short g_rank[NE];              // per-edge rank within dst list
__device__ int    g_srcid[ET];
__device__ int    g_bsum[128];
__device__ int    g_bbase[128];
__device__ float  g_bnsum[HC];
__device__ float  g_bnsq[HC];

__device__ __forceinline__ float lrelu(float v) { return v > 0.f ? v : NEG_SLOPE * v; }
__device__ __forceinline__ float selh(float4 v, int h) {
    float t01 = (h & 1) ? v.y : v.x;
    float t23 = (h & 1) ? v.w : v.z;
    return (h & 2) ? t23 : t01;
}

// ---------------- fused prep: zero + W->fp16 + u = W @ att^T ----------------
// g_deg initialized to 1: slot 0 of every node's CSR list is its self-loop.
__global__ void prep_kernel(const float* __restrict__ W,
                            const float* __restrict__ att_src,
                            const float* __restrict__ att_dst) {
    int t = blockIdx.x * blockDim.x + threadIdx.x;
    if (t < N_NODES) g_deg[t] = 1;
    if (t < HC) { g_bnsum[t] = 0.f; g_bnsq[t] = 0.f; }
    if (t == 0) g_off[N_NODES] = ET;
    if (t < IN_C * HC) g_Wh[t] = __float2half(W[t]);
    if (t < 1024) {                    // u: [sd][h][k]
        int sd = t >> 9, rem = t & 511, h = rem >> 7, k = rem & 127;
        const float* att = sd ? att_dst : att_src;
        float s = 0.f;
#pragma unroll 16
        for (int c = 0; c < OUT_C; c++)
            s = fmaf(W[k * HC + h * OUT_C + c], att[h * OUT_C + c], s);
        g_u[t] = s;
    }
}

// smem union for the fused heterogeneous kernel
struct GemmSmem {
    __half sA[64 * LDA];
    __half sB[32 * LDB];
    float  sC[8][16 * 24];
};
union FusedSmem {
    GemmSmem g;
    float    su[1024];
};

// ---------------- GEMM body: h = fp16(x @ W) via HMMA ----------------------
__device__ __forceinline__ void gemm_body(const float* __restrict__ x,
                                          GemmSmem* sm, int bid) {
    __half* sA = sm->sA;
    __half* sB = sm->sB;

    const int t = threadIdx.x;
    const int w = t >> 5;
    const int lane = t & 31;
    const int rowBase = bid * 64;
    const int rt2 = w >> 2;            // 0..1: 32-row group
    const int cg = w & 3;              // 0..3: 64-col group

#pragma unroll
    for (int i = 0; i < 8; i++) {
        int idx = t + 256 * i;
        int r = idx >> 5, c4 = idx & 31;
        int grow = rowBase + r;
        float4 v = make_float4(0.f, 0.f, 0.f, 0.f);
        if (grow < N_NODES) v = ((const float4*)x)[(size_t)grow * 32 + c4];
        *(__half2*)&sA[r * LDA + c4 * 4]     = __floats2half2_rn(v.x, v.y);
        *(__half2*)&sA[r * LDA + c4 * 4 + 2] = __floats2half2_rn(v.z, v.w);
    }

    wmma::fragment<wmma::accumulator, 16, 16, 16, float> acc[2][4];
#pragma unroll
    for (int mi = 0; mi < 2; mi++)
#pragma unroll
        for (int ni = 0; ni < 4; ni++) wmma::fill_fragment(acc[mi][ni], 0.f);

#pragma unroll 1
    for (int kc = 0; kc < 4; kc++) {
        __syncthreads();
#pragma unroll
        for (int i = 0; i < 4; i++) {
            int idx = t + 256 * i;
            int r = idx >> 5, c8 = idx & 31;
            *(uint4*)&sB[r * LDB + c8 * 8] =
                ((const uint4*)(g_Wh + (kc * 32 + r) * HC))[c8];
        }
        __syncthreads();
#pragma unroll
        for (int ks = 0; ks < 2; ks++) {
            wmma::fragment<wmma::matrix_a, 16, 16, 16, __half, wmma::row_major> a[2];
#pragma unroll
            for (int mi = 0; mi < 2; mi++)
                wmma::load_matrix_sync(a[mi],
                    &sA[(rt2 * 32 + mi * 16) * LDA + kc * 32 + ks * 16], LDA);
#pragma unroll
            for (int ni = 0; ni < 4; ni++) {
                wmma::fragment<wmma::matrix_b, 16, 16, 16, __half, wmma::row_major> b;
                wmma::load_matrix_sync(b, &sB[ks * 16 * LDB + cg * 64 + ni * 16], LDB);
#pragma unroll
                for (int mi = 0; mi < 2; mi++)
                    wmma::mma_sync(acc[mi][ni], a[mi], b, acc[mi][ni]);
            }
        }
    }

    const int er = lane >> 1;
    const int ec = (lane & 1) * 8;
#pragma unroll
    for (int mi = 0; mi < 2; mi++)
#pragma unroll
    for (int ni = 0; ni < 4; ni++) {
        wmma::store_matrix_sync(&sm->sC[w][0], acc[mi][ni], 24, wmma::mem_row_major);
        __syncwarp();
        float4 v0 = *(float4*)&sm->sC[w][er * 24 + ec];
        float4 v1 = *(float4*)&sm->sC[w][er * 24 + ec + 4];
        int grow = rowBase + rt2 * 32 + mi * 16 + er;  // may hit pad rows (safe)
        uint4 u;
        *(__half2*)&u.x = __floats2half2_rn(v0.x, v0.y);
        *(__half2*)&u.y = __floats2half2_rn(v0.z, v0.w);
        *(__half2*)&u.z = __floats2half2_rn(v1.x, v1.y);
        *(__half2*)&u.w = __floats2half2_rn(v1.z, v1.w);
        *(uint4*)&g_hh[(size_t)grow * HC + cg * 64 + ni * 16 + ec] = u;
        __syncwarp();
    }
}

// ---------------- hist body: degree count + per-edge rank ------------------
__device__ __forceinline__ void hist_body(const int* __restrict__ ei, int bid) {
    int t = bid * 256 + threadIdx.x;
    if (t >= NE / 4) return;
    int4 d = ((const int4*)(ei + NE))[t];
    unsigned short r0 = 0, r1 = 0, r2 = 0, r3 = 0;
    if ((unsigned)d.x < N_NODES) r0 = (unsigned short)atomicAdd(&g_deg[d.x], 1);
    if ((unsigned)d.y < N_NODES) r1 = (unsigned short)atomicAdd(&g_deg[d.y], 1);
    if ((unsigned)d.z < N_NODES) r2 = (unsigned short)atomicAdd(&g_deg[d.z], 1);
    if ((unsigned)d.w < N_NODES) r3 = (unsigned short)atomicAdd(&g_deg[d.w], 1);
    ushort4 rr; rr.x = r0; rr.y = r1; rr.z = r2; rr.w = r3;
    ((ushort4*)g_rank)[t] = rr;
}

// ---------------- dots body: a = x @ u (warp per node) ---------------------
__device__ __forceinline__ void dots_body(const float* __restrict__ x,
                                          float* su, int bid) {
    int t = threadIdx.x;
#pragma unroll
    for (int i = 0; i < 4; i++) su[t + 256 * i] = g_u[t + 256 * i];
    __syncthreads();

    int node = bid * 8 + (t >> 5);
    if (node >= N_NODES) return;
    int lane = t & 31;
    float4 xv = ((const float4*)x)[(size_t)node * 32 + lane];
    int k0 = lane * 4;
    float s[4], d[4];
#pragma unroll
    for (int h = 0; h < 4; h++) {
        float4 us = *(float4*)&su[h * 128 + k0];
        float4 ud = *(float4*)&su[512 + h * 128 + k0];
        s[h] = xv.x * us.x + xv.y * us.y + xv.z * us.z + xv.w * us.w;
        d[h] = xv.x * ud.x + xv.y * ud.y + xv.z * ud.z + xv.w * ud.w;
    }
#pragma unroll
    for (int o = 16; o; o >>= 1) {
#pragma unroll
        for (int h = 0; h < 4; h++) {
            s[h] += __shfl_xor_sync(0xffffffffu, s[h], o);
            d[h] += __shfl_xor_sync(0xffffffffu, d[h], o);
        }
    }
    if (lane == 0) {
        g_asrc[node] = make_float4(s[0], s[1], s[2], s[3]);
        g_adst[node] = make_float4(d[0], d[1], d[2], d[3]);
    }
}

// ---------------- fused heterogeneous launch: gemm | hist | dots -----------
__global__ void __launch_bounds__(256) fused_kernel(const float* __restrict__ x,
                                                    const int* __restrict__ ei) {
    __shared__ FusedSmem sm;
    int b = blockIdx.x;
    if (b < GEMM_BLOCKS) {
        gemm_body(x, &sm.g, b);
    } else if (b < GEMM_BLOCKS + HIST_BLOCKS) {
        hist_body(ei, b - GEMM_BLOCKS);
    } else {
        dots_body(x, sm.su, b - GEMM_BLOCKS - HIST_BLOCKS);
    }
}

// ---------------- scans ----------------
__global__ void __launch_bounds__(1024) scan1_kernel() {
    __shared__ int s[1024];
    int t = threadIdx.x;
    int gi = blockIdx.x * 1024 + t;
    int d = (gi < N_NODES) ? g_deg[gi] : 0;
    int v = d;
    s[t] = v;
    __syncthreads();
#pragma unroll
    for (int o = 1; o < 1024; o <<= 1) {
        int add = (t >= o) ? s[t - o] : 0;
        __syncthreads();
        v += add;
        s[t] = v;
        __syncthreads();
    }
    if (gi < N_NODES) g_off[gi] = v - d;
    if (t == 1023) g_bsum[blockIdx.x] = v;
}

__global__ void scan2_kernel() {
    __shared__ int s[128];
    const int NB = (N_NODES + 1023) / 1024;
    int t = threadIdx.x;
    int d = (t < NB) ? g_bsum[t] : 0;
    int v = d;
    s[t] = v;
    __syncthreads();
#pragma unroll
    for (int o = 1; o < 128; o <<= 1) {
        int add = (t >= o) ? s[t - o] : 0;
        __syncthreads();
        v += add;
        s[t] = v;
        __syncthreads();
    }
    if (t < NB) g_bbase[t] = v - d;
}

__global__ void __launch_bounds__(1024) scan3_kernel() {
    int t = threadIdx.x;
    int gi = blockIdx.x * 1024 + t;
    if (gi < N_NODES) g_off[gi] = g_off[gi] + g_bbase[blockIdx.x];
}

// fill: NO atomics. srcid[off[dst]+rank] = src; self-loop in slot 0.
__global__ void fill_kernel(const int* __restrict__ ei) {
    int t = blockIdx.x * blockDim.x + threadIdx.x;
    if (t < NE / 4) {
        int4 s4 = ((const int4*)ei)[t];
        int4 d4 = ((const int4*)(ei + NE))[t];
        ushort4 rr = ((const ushort4*)g_rank)[t];
        if ((unsigned)d4.x < N_NODES)
            g_srcid[g_off[d4.x] + rr.x] = ((unsigned)s4.x < N_NODES) ? s4.x : 0;
        if ((unsigned)d4.y < N_NODES)
            g_srcid[g_off[d4.y] + rr.y] = ((unsigned)s4.y < N_NODES) ? s4.y : 0;
        if ((unsigned)d4.z < N_NODES)
            g_srcid[g_off[d4.z] + rr.z] = ((unsigned)s4.z < N_NODES) ? s4.z : 0;
        if ((unsigned)d4.w < N_NODES)
            g_srcid[g_off[d4.w] + rr.w] = ((unsigned)s4.w < N_NODES) ? s4.w : 0;
    } else {
        int n = t - NE / 4;
        if (n < N_NODES) g_srcid[g_off[n]] = n;     // self loop, slot 0
    }
}

// ---------------- SINGLE-PASS aggregation: one warp per dst node -----------
__device__ __forceinline__ void acc8(float* acc, uint4 hv, float wm) {
    float2 f0 = __half22float2(*(__half2*)&hv.x);
    float2 f1 = __half22float2(*(__half2*)&hv.y);
    float2 f2 = __half22float2(*(__half2*)&hv.z);
    float2 f3 = __half22float2(*(__half2*)&hv.w);
    acc[0] = fmaf(f0.x, wm, acc[0]); acc[1] = fmaf(f0.y, wm, acc[1]);
    acc[2] = fmaf(f1.x, wm, acc[2]); acc[3] = fmaf(f1.y, wm, acc[3]);
    acc[4] = fmaf(f2.x, wm, acc[4]); acc[5] = fmaf(f2.y, wm, acc[5]);
    acc[6] = fmaf(f3.x, wm, acc[6]); acc[7] = fmaf(f3.y, wm, acc[7]);
}

__global__ void __launch_bounds__(256) agg_kernel(const float* __restrict__ bias,
                                                  float* __restrict__ out) {
    const int lane = threadIdx.x & 31;
    const int wpb = blockDim.x >> 5;
    const int wib = threadIdx.x >> 5;
    const int warp = blockIdx.x * wpb + wib;
    const int nwarps = gridDim.x * wpb;
    const int hsel = lane & 3;       // head this lane computes exp for
    const int hmy = lane >> 3;       // head of this lane's 8 channels

    float bnsum[8], bnsq[8], biasv[8];
#pragma unroll
    for (int q = 0; q < 8; q++) {
        bnsum[q] = 0.f; bnsq[q] = 0.f;
        biasv[q] = bias[lane * 8 + q];
    }

    for (int node = warp; node < N_NODES; node += nwarps) {
        const int beg = g_off[node];
        const int end = g_off[node + 1];
        const float adv = selh(g_adst[node], hsel);

        float wsum = 0.f;                 // partial denom for head hsel
        float acc[8];
#pragma unroll
        for (int q = 0; q < 8; q++) acc[q] = 0.f;

        for (int e32 = beg; e32 < end; e32 += 32) {
            int cnt = end - e32; if (cnt > 32) cnt = 32;
            int sv = (lane < cnt) ? g_srcid[e32 + lane] : 0;
#pragma unroll
            for (int sub = 0; sub < 4; sub++) {
                if (sub * 8 >= cnt) break;
                int myj = sub * 8 + (lane >> 2);      // my edge in batch
                int sj = __shfl_sync(0xffffffffu, sv, myj);
                float av = ((const float*)g_asrc)[sj * 4 + hsel];
                float wv = (myj < cnt) ? __expf(lrelu(av + adv)) : 0.f;
                wsum += wv;
#pragma unroll
                for (int j = 0; j < 8; j++) {
                    float wm = __shfl_sync(0xffffffffu, wv, j * 4 + hmy);
                    int sb = __shfl_sync(0xffffffffu, sv, sub * 8 + j);
                    uint4 hv = ((const uint4*)(g_hh + (size_t)sb * HC))[lane];
                    acc8(acc, hv, wm);               // wm==0 for padded edges
                }
            }
        }

        // denom: sum lanes sharing hsel (xor 4,8,16)
#pragma unroll
        for (int o = 4; o < 32; o <<= 1)
            wsum += __shfl_xor_sync(0xffffffffu, wsum, o);
        float inv = 1.f / (wsum + 1e-16f);
        float invm = __shfl_sync(0xffffffffu, inv, hmy);  // lane hmy holds head hmy

        float v[8];
#pragma unroll
        for (int q = 0; q < 8; q++) {
            v[q] = fmaf(acc[q], invm, biasv[q]);
            bnsum[q] += v[q];
            bnsq[q] = fmaf(v[q], v[q], bnsq[q]);
        }
        float4* op4 = (float4*)(out + (size_t)node * HC);
        op4[lane * 2]     = make_float4(v[0], v[1], v[2], v[3]);
        op4[lane * 2 + 1] = make_float4(v[4], v[5], v[6], v[7]);
    }

    // ---- block-level BN partial reduction (channel c = lane*8+q) ----
    __shared__ float s_sum[8][HC];
    __shared__ float s_sq[8][HC];
    {
        float4* ss = (float4*)s_sum[wib];
        float4* sq = (float4*)s_sq[wib];
        ss[lane * 2]     = make_float4(bnsum[0], bnsum[1], bnsum[2], bnsum[3]);
        ss[lane * 2 + 1] = make_float4(bnsum[4], bnsum[5], bnsum[6], bnsum[7]);
        sq[lane * 2]     = make_float4(bnsq[0], bnsq[1], bnsq[2], bnsq[3]);
        sq[lane * 2 + 1] = make_float4(bnsq[4], bnsq[5], bnsq[6], bnsq[7]);
    }
    __syncthreads();
    {
        int c = threadIdx.x;
        float ts = 0.f, tq = 0.f;
#pragma unroll
        for (int w = 0; w < 8; w++) { ts += s_sum[w][c]; tq += s_sq[w][c]; }
        atomicAdd(&g_bnsum[c], ts);
        atomicAdd(&g_bnsq[c], tq);
    }
}

// ---------------- BatchNorm + ELU epilogue (float4) ----------------
__global__ void bn_elu_kernel(const float* __restrict__ gamma,
                              const float* __restrict__ beta,
                              float* __restrict__ out) {
    int idx = blockIdx.x * blockDim.x + threadIdx.x;     // over N*HC/4
    if (idx >= N_NODES * (HC / 4)) return;
    int c0 = (idx & 63) * 4;
    const float invN = 1.f / (float)N_NODES;
    float4 v = ((const float4*)out)[idx];
    float r[4] = {v.x, v.y, v.z, v.w};
#pragma unroll
    for (int q = 0; q < 4; q++) {
        int c = c0 + q;
        float mean = g_bnsum[c] * invN;
        float var = g_bnsq[c] * invN - mean * mean;
        float y = gamma[c] * (r[q] - mean) * rsqrtf(var + BN_EPS) + beta[c];
        r[q] = y > 0.f ? y : expm1f(y);
    }
    ((float4*)out)[idx] = make_float4(r[0], r[1], r[2], r[3]);
}

// ---------------- launch ----------------
extern "C" void kernel_launch(void* const* d_in, const int* in_sizes, int n_in,
                              void* d_out, int out_size) {
    const float* x       = (const float*)d_in[0];
    const int*   ei      = (const int*)d_in[1];     // JAX x64 disabled => int32
    const float* W       = (const float*)d_in[2];
    const float* att_src = (const float*)d_in[3];
    const float* att_dst = (const float*)d_in[4];
    const float* bias    = (const float*)d_in[5];
    const float* gamma   = (const float*)d_in[6];
    const float* beta    = (const float*)d_in[7];
    float* out = (float*)d_out;

    prep_kernel<<<(N_NODES + 255) / 256, 256>>>(W, att_src, att_dst);
    fused_kernel<<<FUSED_BLOCKS, 256>>>(x, ei);
    scan1_kernel<<<(N_NODES + 1023) / 1024, 1024>>>();
    scan2_kernel<<<1, 128>>>();
    scan3_kernel<<<(N_NODES + 1023) / 1024, 1024>>>();
    fill_kernel<<<(NE / 4 + N_NODES + 255) / 256, 256>>>(ei);
    agg_kernel<<<2048, 256>>>(bias, out);
    bn_elu_kernel<<<(N_NODES * (HC / 4) + 255) / 256, 256>>>(gamma, beta, out);
}